// round 16
// baseline (speedup 1.0000x reference)
#include <cuda_runtime.h>
#include <cuda_fp16.h>
#include <math.h>
#include <stdint.h>

#define NSEQ  4096
#define CDIM  64
#define MT    64
#define KB    64
#define KSPLIT 8
#define KHALF (NSEQ / KSPLIT)      // 512
#define NBLK  (KHALF / KB)         // 8

// scratch (allocation-free rule -> __device__ globals)
__device__ __half g_xh[2 * NSEQ * CDIM];
__device__ __half g_Opart[2 * KSPLIT * NSEQ * CDIM];
__device__ float  g_lpart[2 * KSPLIT * NSEQ];
__device__ float  g_mpart[2 * KSPLIT * NSEQ];

// smem layout (bytes): QH 64x128B (8KB); X hi double-buffered 64x128B (8KB per buf)
#define QH_OFF 0u
#define XB_OFF 8192u               // buf b at XB_OFF + b*8192
#define SMEM_BYTES 24576u          // 24KB -> 4 CTAs/SM (reg-capped)

__device__ __forceinline__ uint32_t cvta_smem(const void* p) {
    uint32_t a;
    asm("{ .reg .u64 t; cvta.to.shared.u64 t, %1; cvt.u32.u64 %0, t; }" : "=r"(a) : "l"(p));
    return a;
}
__device__ __forceinline__ void ldsm4(uint32_t addr, uint32_t* r) {
    asm volatile("ldmatrix.sync.aligned.m8n8.x4.shared.b16 {%0,%1,%2,%3}, [%4];"
                 : "=r"(r[0]), "=r"(r[1]), "=r"(r[2]), "=r"(r[3]) : "r"(addr));
}
__device__ __forceinline__ void ldsm4t(uint32_t addr, uint32_t* r) {
    asm volatile("ldmatrix.sync.aligned.m8n8.x4.trans.shared.b16 {%0,%1,%2,%3}, [%4];"
                 : "=r"(r[0]), "=r"(r[1]), "=r"(r[2]), "=r"(r[3]) : "r"(addr));
}
__device__ __forceinline__ void mma16816(float* c, const uint32_t* a, const uint32_t* b) {
    asm volatile("mma.sync.aligned.m16n8k16.row.col.f32.f16.f16.f32 "
                 "{%0,%1,%2,%3}, {%4,%5,%6,%7}, {%8,%9}, {%0,%1,%2,%3};"
                 : "+f"(c[0]), "+f"(c[1]), "+f"(c[2]), "+f"(c[3])
                 : "r"(a[0]), "r"(a[1]), "r"(a[2]), "r"(a[3]), "r"(b[0]), "r"(b[1]));
}
__device__ __forceinline__ void cp16(uint32_t dst, const void* src) {
    asm volatile("cp.async.cg.shared.global [%0], [%1], 16;" :: "r"(dst), "l"(src));
}
#define CP_COMMIT()  asm volatile("cp.async.commit_group;" ::: "memory")
#define CP_WAIT(n)   asm volatile("cp.async.wait_group %0;" :: "n"(n) : "memory")

// XOR-swizzled byte offset inside a 128B-row tile
__device__ __forceinline__ uint32_t swz(uint32_t tb, int row, int cb) {
    return tb + row * 128 + (((((unsigned)cb >> 4) ^ (row & 7)) << 4) | (cb & 15));
}

// ---- pre-pass: cast fp32 x to fp16 (8 independent float4s per thread, MLP=8) ----
__global__ __launch_bounds__(256) void split_kernel(const float* __restrict__ x)
{
    const int base = blockIdx.x * 2048 + threadIdx.x;   // 64 blocks cover 131072 float4s
    float4 v[8];
    #pragma unroll
    for (int k = 0; k < 8; ++k) v[k] = ((const float4*)x)[base + k * 256];
    #pragma unroll
    for (int k = 0; k < 8; ++k) {
        __half2 H0 = __floats2half2_rn(v[k].x, v[k].y);
        __half2 H1 = __floats2half2_rn(v[k].z, v[k].w);
        ((uint2*)g_xh)[base + k * 256] = make_uint2(*(uint32_t*)&H0, *(uint32_t*)&H1);
    }
}

__global__ __launch_bounds__(128, 4) void attn_main()
{
    extern __shared__ char sm[];
    const uint32_t sb = cvta_smem(sm);
    const int tid = threadIdx.x, lane = tid & 31, w = tid >> 5;
    const int qb = blockIdx.x * MT, b = blockIdx.y, kh = blockIdx.z;
    const __half* xh = g_xh + (size_t)b * NSEQ * CDIM;

    // prologue: Q hi + X block 0 via cp.async (one group)
    {
        const int row = tid >> 1, h = tid & 1;
        const size_t qrow = (size_t)(qb + row) * CDIM + h * 32;
        const size_t xrow = (size_t)(kh * KHALF + row) * CDIM + h * 32;
        #pragma unroll
        for (int i = 0; i < 4; ++i) {
            const int cb = h * 64 + i * 16;     // byte col within 128B row
            cp16(swz(sb + QH_OFF, row, cb), xh + qrow + i * 8);
            cp16(swz(sb + XB_OFF, row, cb), xh + xrow + i * 8);
        }
        CP_COMMIT();
    }
    CP_WAIT(0);
    __syncthreads();

    const int r0 = w * 16;
    const int g = lane >> 3, lr = lane & 7;

    // ---- hoisted Q-hi fragments (loop-invariant; QH never overwritten) ----
    uint32_t aH[4][4];
    {
        const int arow = r0 + (g & 1) * 8 + lr;
        const int acb  = (g >> 1) * 16;
        #pragma unroll
        for (int k = 0; k < 4; ++k)
            ldsm4(swz(sb + QH_OFF, arow, k * 32 + acb), aH[k]);
    }

    float m0 = -1e30f, m1 = -1e30f, l0 = 0.f, l1 = 0.f;
    float O[8][4];
    #pragma unroll
    for (int jc = 0; jc < 8; ++jc)
        #pragma unroll
        for (int q = 0; q < 4; ++q) O[jc][q] = 0.f;

    for (int blk = 0; blk < NBLK; ++blk) {
        const uint32_t XH = sb + XB_OFF + (blk & 1) * 8192u;

        // issue next block's loads into the other buffer
        if (blk + 1 < NBLK) {
            const uint32_t NH = sb + XB_OFF + ((blk + 1) & 1) * 8192u;
            const int row = tid >> 1, h = tid & 1;
            const size_t xrow = (size_t)(kh * KHALF + (blk + 1) * KB + row) * CDIM + h * 32;
            #pragma unroll
            for (int i = 0; i < 4; ++i)
                cp16(swz(NH, row, h * 64 + i * 16), xh + xrow + i * 8);
            CP_COMMIT();
            CP_WAIT(1);
        } else {
            CP_WAIT(0);
        }
        __syncthreads();

        // ---- GEMM1: S = Qh * Xh (pure fp16 operands, f32 acc) ----
        float S[8][4];
        #pragma unroll
        for (int j = 0; j < 8; ++j) {
            const int krow = j * 8 + lr;
            uint32_t t0[4], t1[4];
            ldsm4(swz(XH, krow, g * 16), t0);
            ldsm4(swz(XH, krow, 64 + g * 16), t1);
            uint32_t bh[4][2] = {{t0[0],t0[1]},{t0[2],t0[3]},{t1[0],t1[1]},{t1[2],t1[3]}};
            S[j][0] = 0.f; S[j][1] = 0.f; S[j][2] = 0.f; S[j][3] = 0.f;
            #pragma unroll
            for (int k = 0; k < 4; ++k)
                mma16816(S[j], aH[k], bh[k]);
        }

        // ---- online softmax (rows: ra = lane/4, rb = ra+8) ----
        float mx0 = -1e30f, mx1 = -1e30f;
        #pragma unroll
        for (int j = 0; j < 8; ++j) {
            mx0 = fmaxf(mx0, fmaxf(S[j][0], S[j][1]));
            mx1 = fmaxf(mx1, fmaxf(S[j][2], S[j][3]));
        }
        mx0 = fmaxf(mx0, __shfl_xor_sync(0xffffffffu, mx0, 1));
        mx0 = fmaxf(mx0, __shfl_xor_sync(0xffffffffu, mx0, 2));
        mx1 = fmaxf(mx1, __shfl_xor_sync(0xffffffffu, mx1, 1));
        mx1 = fmaxf(mx1, __shfl_xor_sync(0xffffffffu, mx1, 2));
        const float mn0 = fmaxf(m0, mx0), mn1 = fmaxf(m1, mx1);
        const float cr0 = __expf(m0 - mn0), cr1 = __expf(m1 - mn1);
        m0 = mn0; m1 = mn1;

        float s0 = 0.f, s1 = 0.f;
        uint32_t Ph[8][2];
        #pragma unroll
        for (int j = 0; j < 8; ++j) {
            float p0 = __expf(S[j][0] - mn0), p1 = __expf(S[j][1] - mn0);
            float p2 = __expf(S[j][2] - mn1), p3 = __expf(S[j][3] - mn1);
            s0 += p0 + p1; s1 += p2 + p3;
            __half2 H0 = __floats2half2_rn(p0, p1), H1 = __floats2half2_rn(p2, p3);
            Ph[j][0] = *(uint32_t*)&H0; Ph[j][1] = *(uint32_t*)&H1;
        }
        s0 += __shfl_xor_sync(0xffffffffu, s0, 1);
        s0 += __shfl_xor_sync(0xffffffffu, s0, 2);
        s1 += __shfl_xor_sync(0xffffffffu, s1, 1);
        s1 += __shfl_xor_sync(0xffffffffu, s1, 2);
        l0 = l0 * cr0 + s0; l1 = l1 * cr1 + s1;
        #pragma unroll
        for (int jc = 0; jc < 8; ++jc) {
            O[jc][0] *= cr0; O[jc][1] *= cr0; O[jc][2] *= cr1; O[jc][3] *= cr1;
        }

        // ---- GEMM2: O[16 rows][64 ch] += Ph[16][64] * Vh[64][64] ----
        #pragma unroll
        for (int jc = 0; jc < 8; ++jc) {
            uint32_t vh[4][2];
            #pragma unroll
            for (int kp = 0; kp < 2; ++kp) {
                uint32_t t[4];
                const int key = kp * 32 + g * 8 + lr;
                ldsm4t(swz(XH, key, jc * 16), t);
                vh[2*kp][0] = t[0]; vh[2*kp][1] = t[1];
                vh[2*kp+1][0] = t[2]; vh[2*kp+1][1] = t[3];
            }
            #pragma unroll
            for (int kk = 0; kk < 4; ++kk) {
                uint32_t Ah[4] = {Ph[2*kk][0], Ph[2*kk][1], Ph[2*kk+1][0], Ph[2*kk+1][1]};
                mma16816(O[jc], Ah, vh[kk]);
            }
        }
        __syncthreads();   // all warps done with this buffer before it is overwritten
    }

    // ---- write per-split partials (O in fp16) ----
    const int ra = qb + r0 + (lane >> 2);
    const size_t pb = (size_t)(b * KSPLIT + kh) * NSEQ;
    if ((lane & 3) == 0) {
        g_mpart[pb + ra] = m0;     g_lpart[pb + ra] = l0;
        g_mpart[pb + ra + 8] = m1; g_lpart[pb + ra + 8] = l1;
    }
    #pragma unroll
    for (int jc = 0; jc < 8; ++jc) {
        const int ch = jc * 8 + 2 * (lane & 3);
        __half2 a = __floats2half2_rn(O[jc][0], O[jc][1]);
        __half2 c = __floats2half2_rn(O[jc][2], O[jc][3]);
        *(__half2*)&g_Opart[(pb + ra) * CDIM + ch]     = a;
        *(__half2*)&g_Opart[(pb + ra + 8) * CDIM + ch] = c;
    }
}

// ---- merge: each thread produces 2 float4s, amortizing the row reduction ----
__global__ __launch_bounds__(256) void merge_kernel(const float* __restrict__ x,
                                                    const float* __restrict__ gamma,
                                                    float* __restrict__ out)
{
    const int i  = blockIdx.x * 256 + threadIdx.x;     // 65536 threads
    const int c4 = i & 7;                              // handles c4 and c4+8
    const int r  = (i >> 3) & (NSEQ - 1);
    const int b  = i >> 15;

    // row-level reduction (once per 2 outputs)
    float mv[KSPLIT];
    float M = -1e30f;
    #pragma unroll
    for (int s = 0; s < KSPLIT; ++s) {
        mv[s] = g_mpart[(size_t)(b * KSPLIT + s) * NSEQ + r];
        M = fmaxf(M, mv[s]);
    }
    float ws[KSPLIT];
    float den = 0.f;
    #pragma unroll
    for (int s = 0; s < KSPLIT; ++s) {
        ws[s] = __expf(mv[s] - M);
        den += ws[s] * g_lpart[(size_t)(b * KSPLIT + s) * NSEQ + r];
    }
    const float gscale = gamma[0] / den;

    float4 acc0 = make_float4(0.f, 0.f, 0.f, 0.f);
    float4 acc1 = make_float4(0.f, 0.f, 0.f, 0.f);
    #pragma unroll
    for (int s = 0; s < KSPLIT; ++s) {
        const size_t p = ((size_t)(b * KSPLIT + s) * NSEQ + r) * CDIM;
        const __half2* oa = (const __half2*)&g_Opart[p + c4 * 4];
        const __half2* ob = (const __half2*)&g_Opart[p + (c4 + 8) * 4];
        const float2 a01 = __half22float2(oa[0]), a23 = __half22float2(oa[1]);
        const float2 b01 = __half22float2(ob[0]), b23 = __half22float2(ob[1]);
        const float w = ws[s];
        acc0.x += w * a01.x; acc0.y += w * a01.y; acc0.z += w * a23.x; acc0.w += w * a23.y;
        acc1.x += w * b01.x; acc1.y += w * b01.y; acc1.z += w * b23.x; acc1.w += w * b23.y;
    }
    const size_t orow = ((size_t)b * NSEQ + r) * CDIM;
    const float4 xv0 = ((const float4*)&x[orow])[c4];
    const float4 xv1 = ((const float4*)&x[orow])[c4 + 8];
    float4 o0, o1;
    o0.x = gscale * acc0.x + xv0.x; o0.y = gscale * acc0.y + xv0.y;
    o0.z = gscale * acc0.z + xv0.z; o0.w = gscale * acc0.w + xv0.w;
    o1.x = gscale * acc1.x + xv1.x; o1.y = gscale * acc1.y + xv1.y;
    o1.z = gscale * acc1.z + xv1.z; o1.w = gscale * acc1.w + xv1.w;
    ((float4*)&out[orow])[c4]     = o0;
    ((float4*)&out[orow])[c4 + 8] = o1;
}

extern "C" void kernel_launch(void* const* d_in, const int* in_sizes, int n_in,
                              void* d_out, int out_size)
{
    const float* x     = (const float*)d_in[0];
    const float* gamma = (const float*)d_in[1];
    float* out = (float*)d_out;
    (void)in_sizes; (void)n_in; (void)out_size;

    cudaFuncSetAttribute(attn_main, cudaFuncAttributeMaxDynamicSharedMemorySize, SMEM_BYTES);
    split_kernel<<<64, 256>>>(x);
    attn_main<<<dim3(NSEQ / MT, 2, KSPLIT), 128, SMEM_BYTES>>>();
    merge_kernel<<<256, 256>>>(x, gamma, out);
}